// round 17
// baseline (speedup 1.0000x reference)
#include <cuda_runtime.h>
#include <cuda_fp16.h>
#include <cstdint>

#define B_ 128
#define T_ 500
#define M_ 512
#define L_ 128
#define NROWS (B_ * T_)        // 64000

// ---- GEMM tiling ----
#define RM 64                  // rows per tile
#define NC 256                 // interleaved (v,u) cols
#define KC 64                  // K per chunk
#define NCHUNK (M_ / KC)       // 8
#define ASTRIDE 144            // bytes per A row (128B data + 16 pad)
#define NLONG 112              // CTAs that process 2 tiles
#define GRID 888               // 3 x 296 slots

// per-stage smem layout (A only now)
#define A_HI 0
#define STAGE (RM * ASTRIDE)             // 9216
#define DYN (2 * STAGE)                  // 18432

// ---- persistent device scratch ----
// B in mma fragment order: idx = ((c*4+ks)*16 + g)*32 + lane  (uint4 each)
__device__ uint4 g_Bf[NCHUNK * 4 * 16 * 32];   // 256 KB
__device__ float g_C[NROWS * 2];               // C = H @ Wc
__device__ int   g_cnt[B_];                    // per-bag tile counters

// ============================ helpers ============================
__device__ __forceinline__ uint32_t smem_u32(const void* p) {
    uint32_t a;
    asm("{ .reg .u64 t; cvta.to.shared.u64 t, %1; cvt.u32.u64 %0, t; }" : "=r"(a) : "l"(p));
    return a;
}
__device__ __forceinline__ float fast_sigm(float x) {
    return __fdividef(1.0f, 1.0f + __expf(-x));
}
__device__ __forceinline__ float fast_tanh(float x) {
    float t = __expf(2.0f * x);
    return 1.0f - __fdividef(2.0f, t + 1.0f);
}

__device__ __forceinline__ void ldsm_x4(uint32_t (&r)[4], uint32_t addr) {
    asm volatile("ldmatrix.sync.aligned.m8n8.x4.shared.b16 {%0,%1,%2,%3}, [%4];"
                 : "=r"(r[0]), "=r"(r[1]), "=r"(r[2]), "=r"(r[3]) : "r"(addr));
}
__device__ __forceinline__ void mma_f16(float (&c)[4], const uint32_t (&a)[4],
                                        uint32_t b0, uint32_t b1) {
    asm volatile(
        "mma.sync.aligned.m16n8k16.row.col.f32.f16.f16.f32 "
        "{%0,%1,%2,%3}, {%4,%5,%6,%7}, {%8,%9}, {%0,%1,%2,%3};"
        : "+f"(c[0]), "+f"(c[1]), "+f"(c[2]), "+f"(c[3])
        : "r"(a[0]), "r"(a[1]), "r"(a[2]), "r"(a[3]), "r"(b0), "r"(b1));
}
__device__ __forceinline__ uint32_t pack2h(__half a, __half b) {
    unsigned short ra = *(unsigned short*)&a, rb = *(unsigned short*)&b;
    return (uint32_t)ra | ((uint32_t)rb << 16);
}

// ============================================================================
// prep v5: write B directly in mma fragment order + counter reset.
// For fragment u: t=u&31, g=(u>>5)&15, ks=(u>>9)&3, c=u>>11.
//   n1 = 16g + t/4, n2 = n1+8, kb = 64c + 16ks + 2(t&3)
//   uint4 = { (n1,kb|kb+1), (n1,kb+8|kb+9), (n2,kb|kb+1), (n2,kb+8|kb+9) }
// where value(n,k) = (n odd ? Wu : Wv)[k][n>>1]  (interleaved v,u columns).
// grid = 64 x 256.
// ============================================================================
__global__ void __launch_bounds__(256) prep_kernel(
    const float* __restrict__ Wv, const float* __restrict__ Wu)
{
    const int tid = threadIdx.x;
    if (blockIdx.x == 0 && tid < B_) g_cnt[tid] = 0;

    const int u  = blockIdx.x * 256 + tid;
    const int t  = u & 31;
    const int g  = (u >> 5) & 15;
    const int ks = (u >> 9) & 3;
    const int c  = u >> 11;

    const int n1 = g * 16 + (t >> 2);
    const int n2 = n1 + 8;
    const int kb = c * 64 + ks * 16 + 2 * (t & 3);

    const int j1 = n1 >> 1, j2 = n2 >> 1;
    const float* p1 = (n1 & 1) ? Wu : Wv;
    const float* p2 = (n2 & 1) ? Wu : Wv;

    __half h00 = __float2half_rn(p1[(kb + 0) * L_ + j1]);
    __half h01 = __float2half_rn(p1[(kb + 1) * L_ + j1]);
    __half h10 = __float2half_rn(p1[(kb + 8) * L_ + j1]);
    __half h11 = __float2half_rn(p1[(kb + 9) * L_ + j1]);
    __half h20 = __float2half_rn(p2[(kb + 0) * L_ + j2]);
    __half h21 = __float2half_rn(p2[(kb + 1) * L_ + j2]);
    __half h30 = __float2half_rn(p2[(kb + 8) * L_ + j2]);
    __half h31 = __float2half_rn(p2[(kb + 9) * L_ + j2]);

    g_Bf[u] = make_uint4(pack2h(h00, h01), pack2h(h10, h11),
                         pack2h(h20, h21), pack2h(h30, h31));
}

// ============================================================================
// GEMM (fp16 mma.sync, B fragments via direct LDG) + gate/Wa epilogue +
// fp32 C=H@Wc + fused per-bag pool. grid = 888 (112 long CTAs x 2 tiles).
// Only A is staged in smem (18 KB dyn) -> L1D carveout ~210 KB keeps B hot.
// ============================================================================
__global__ void __launch_bounds__(256, 2) gemm_attn_kernel(
    const float* __restrict__ H,  const float* __restrict__ bv,
    const float* __restrict__ bu, const float* __restrict__ Wa,
    const float* __restrict__ ba, const float* __restrict__ Wc,
    const float* __restrict__ bc,
    float* __restrict__ A_raw, float* __restrict__ A_sm,
    float* __restrict__ out)
{
    extern __shared__ char sm[];
    __shared__ float bvS[L_], buS[L_], WaS[L_];
    __shared__ float Wc0S[M_], Wc1S[M_];
    __shared__ float red[RM][4];
    __shared__ int   do_bag[2];
    __shared__ float pr[8], prB[8];
    __shared__ float sh_mx, sh_sum;

    const int tid  = threadIdx.x;
    const int lane = tid & 31;
    const int warp = tid >> 5;
    const int wm   = warp >> 2;      // 0..1
    const int wn   = warp & 3;       // 0..3
    const int bid  = blockIdx.x;
    const int nsub  = (bid < NLONG) ? 2 : 1;
    const int tile0 = (bid < NLONG) ? (2 * bid) : (NLONG + bid);
    const int rot = ((bid / 148) & 1) << 2;   // co-resident CTA desync
#define CH(c) ((c) ^ rot)

    if (tid < L_) { bvS[tid] = bv[tid]; buS[tid] = bu[tid]; WaS[tid] = Wa[tid]; }
#pragma unroll
    for (int i = 0; i < 2; i++) {
        int k = i * 256 + tid;
        Wc0S[k] = Wc[2 * k];
        Wc1S[k] = Wc[2 * k + 1];
    }

    float acc[2][8][4];
    float4 ar[4];                    // A staging regs (fp32, also feeds C)
    float cc[4][2];                  // fp32 C accumulators

    const uint32_t smb = smem_u32(sm);

    const uint32_t a_ld_row  = (uint32_t)(wm * 32 + (lane & 15));
    const uint32_t a_ld_koff = (uint32_t)((lane >> 4) * 16);
    const uint32_t a_base_off = A_HI + a_ld_row * ASTRIDE + a_ld_koff;

    // per-thread B fragment base: idx = c*2048 + ks*512 + wn*128 + p*32 + lane
    const uint4* bf_base = (const uint4*)g_Bf + wn * 128 + lane;

    const int c_f4 = tid & 15;

#define LOADG_A(c)                                                                 \
    {                                                                              \
        const int kt = (c) * KC;                                                   \
        _Pragma("unroll")                                                          \
        for (int i = 0; i < 4; i++) {                                              \
            int idx = i * 256 + tid;                                               \
            int row = idx >> 4, f4 = idx & 15;                                     \
            ar[i] = *(const float4*)(H + (n0 + row) * M_ + kt + f4 * 4);           \
        }                                                                          \
    }

#define C_ACCUM(c)                                                                 \
    {                                                                              \
        const int kb = (c) * KC + c_f4 * 4;                                        \
        float w00 = Wc0S[kb], w01 = Wc0S[kb + 1], w02 = Wc0S[kb + 2], w03 = Wc0S[kb + 3]; \
        float w10 = Wc1S[kb], w11 = Wc1S[kb + 1], w12 = Wc1S[kb + 2], w13 = Wc1S[kb + 3]; \
        _Pragma("unroll")                                                          \
        for (int i = 0; i < 4; i++) {                                              \
            cc[i][0] = fmaf(ar[i].x, w00, cc[i][0]);                               \
            cc[i][0] = fmaf(ar[i].y, w01, cc[i][0]);                               \
            cc[i][0] = fmaf(ar[i].z, w02, cc[i][0]);                               \
            cc[i][0] = fmaf(ar[i].w, w03, cc[i][0]);                               \
            cc[i][1] = fmaf(ar[i].x, w10, cc[i][1]);                               \
            cc[i][1] = fmaf(ar[i].y, w11, cc[i][1]);                               \
            cc[i][1] = fmaf(ar[i].z, w12, cc[i][1]);                               \
            cc[i][1] = fmaf(ar[i].w, w13, cc[i][1]);                               \
        }                                                                          \
    }

#define STORE_A(buf)                                                               \
    {                                                                              \
        char* sb = sm + (buf) * STAGE;                                             \
        _Pragma("unroll")                                                          \
        for (int i = 0; i < 4; i++) {                                              \
            int idx = i * 256 + tid;                                               \
            int row = idx >> 4, f4 = idx & 15;                                     \
            float4 x = ar[i];                                                      \
            __half h0 = __float2half_rn(x.x), h1 = __float2half_rn(x.y);           \
            __half h2 = __float2half_rn(x.z), h3 = __float2half_rn(x.w);           \
            uint32_t off = (uint32_t)(row * ASTRIDE + f4 * 8);                     \
            *(uint2*)(sb + A_HI + off) = make_uint2(pack2h(h0, h1), pack2h(h2, h3)); \
        }                                                                          \
    }

// COMPUTE v3: A via ldsm from smem; B fragments via direct coalesced LDG.128
// from g_Bf (L1/L2-hot), double-buffered one (ks,p)-step ahead.
#define COMPUTE(buf, cidx)                                                         \
    {                                                                              \
        const uint32_t a_base = smb + (buf) * STAGE + a_base_off;                  \
        const uint4* bf = bf_base + (size_t)(cidx) * 2048;                         \
        uint4 bvv[2];                                                              \
        bvv[0] = __ldg(bf);                                                        \
        _Pragma("unroll")                                                          \
        for (int ks = 0; ks < 4; ks++) {                                           \
            uint32_t ah[2][4];                                                     \
            ldsm_x4(ah[0], a_base + ks * 32);                                      \
            ldsm_x4(ah[1], a_base + 16 * ASTRIDE + ks * 32);                       \
            _Pragma("unroll")                                                      \
            for (int p = 0; p < 4; p++) {                                          \
                const int cur = p & 1, nxt = cur ^ 1;                              \
                if (p < 3)                                                         \
                    bvv[nxt] = __ldg(bf + ks * 512 + (p + 1) * 32);                \
                else if (ks < 3)                                                   \
                    bvv[nxt] = __ldg(bf + (ks + 1) * 512);                         \
                mma_f16(acc[0][2 * p],     ah[0], bvv[cur].x, bvv[cur].y);         \
                mma_f16(acc[0][2 * p + 1], ah[0], bvv[cur].z, bvv[cur].w);         \
                mma_f16(acc[1][2 * p],     ah[1], bvv[cur].x, bvv[cur].y);         \
                mma_f16(acc[1][2 * p + 1], ah[1], bvv[cur].z, bvv[cur].w);         \
            }                                                                      \
        }                                                                          \
    }

#pragma unroll 1
    for (int sub = 0; sub < nsub; sub++) {
        const size_t n0 = (size_t)(tile0 + sub) * RM;

#pragma unroll
        for (int mt = 0; mt < 2; mt++)
#pragma unroll
            for (int nt = 0; nt < 8; nt++)
#pragma unroll
                for (int i = 0; i < 4; i++) acc[mt][nt][i] = 0.0f;
#pragma unroll
        for (int i = 0; i < 4; i++) { cc[i][0] = 0.0f; cc[i][1] = 0.0f; }

        // ---- pipelined main loop (A smem double-buffered; B via LDG) ----
        LOADG_A(CH(0));
        __syncthreads();            // Wc0S/Wc1S ready (sub 0) / prior sub done
        C_ACCUM(CH(0));
        STORE_A(0);
        __syncthreads();
#pragma unroll 1
        for (int c = 0; c < NCHUNK; c++) {
            const int buf = c & 1;
            if (c + 1 < NCHUNK) {
                LOADG_A(CH(c + 1));
                C_ACCUM(CH(c + 1));
            }
            COMPUTE(buf, CH(c));
            if (c + 1 < NCHUNK) STORE_A(buf ^ 1);
            __syncthreads();
        }

        // ---- C reduce over the 16-lane k-slice groups, write fp32 C ----
#pragma unroll
        for (int i = 0; i < 4; i++) {
#pragma unroll
            for (int o = 1; o < 16; o <<= 1) {
                cc[i][0] += __shfl_xor_sync(~0u, cc[i][0], o);
                cc[i][1] += __shfl_xor_sync(~0u, cc[i][1], o);
            }
        }
        if (c_f4 == 0) {
            int r0 = tid >> 4;
#pragma unroll
            for (int i = 0; i < 4; i++)
                *(float2*)(g_C + (n0 + r0 + 16 * i) * 2) = make_float2(cc[i][0], cc[i][1]);
        }

        // ---- fused epilogue: gate + Wa dot, in-thread (v,u) pairs ----
#pragma unroll
        for (int mt = 0; mt < 2; mt++) {
            float p0 = 0.0f, p1 = 0.0f;
#pragma unroll
            for (int nt = 0; nt < 8; nt++) {
                int j = wn * 32 + nt * 4 + (lane & 3);
                float bvj = bvS[j], buj = buS[j], waj = WaS[j];
                p0 += fast_tanh(acc[mt][nt][0] + bvj) * fast_sigm(acc[mt][nt][1] + buj) * waj;
                p1 += fast_tanh(acc[mt][nt][2] + bvj) * fast_sigm(acc[mt][nt][3] + buj) * waj;
            }
            p0 += __shfl_xor_sync(~0u, p0, 1); p0 += __shfl_xor_sync(~0u, p0, 2);
            p1 += __shfl_xor_sync(~0u, p1, 1); p1 += __shfl_xor_sync(~0u, p1, 2);
            if ((lane & 3) == 0) {
                int r = wm * 32 + mt * 16 + (lane >> 2);
                red[r][wn] = p0;
                red[r + 8][wn] = p1;
            }
        }
        __syncthreads();
        if (tid < RM) {
            float s = red[tid][0] + red[tid][1] + red[tid][2] + red[tid][3] + __ldg(ba);
            A_raw[n0 + tid] = s;
        }

        // ==== fused per-bag pool: last tile of each bag does softmax+pool ====
        __threadfence();
        __syncthreads();
        if (tid == 0) {
            do_bag[0] = -1; do_bag[1] = -1;
            int bag_lo = (int)(n0 / T_);
            int bag_hi = (int)((n0 + RM - 1) / T_);
            for (int b = bag_lo; b <= bag_hi; b++) {
                int first = (b * T_) / RM;
                int last  = (b * T_ + T_ - 1) / RM;
                int cnt   = last - first + 1;
                if (atomicAdd(&g_cnt[b], 1) == cnt - 1)
                    do_bag[b - bag_lo] = b;
            }
        }
        __syncthreads();

#pragma unroll 1
        for (int s = 0; s < 2; s++) {
            int b = do_bag[s];
            if (b < 0) continue;
            const float* Ab = A_raw + b * T_;
            float a0 = (tid < T_) ? Ab[tid] : -1e30f;
            float a1 = (tid + 256 < T_) ? Ab[tid + 256] : -1e30f;
            float mx = fmaxf(a0, a1);
#pragma unroll
            for (int o = 16; o; o >>= 1) mx = fmaxf(mx, __shfl_xor_sync(~0u, mx, o));
            if (lane == 0) pr[warp] = mx;
            __syncthreads();
            if (tid < 32) {
                float v = (tid < 8) ? pr[tid] : -1e30f;
#pragma unroll
                for (int o = 4; o; o >>= 1) v = fmaxf(v, __shfl_xor_sync(~0u, v, o));
                if (tid == 0) sh_mx = v;
            }
            __syncthreads();
            float e0 = (tid < T_) ? __expf(a0 - sh_mx) : 0.0f;
            float e1 = (tid + 256 < T_) ? __expf(a1 - sh_mx) : 0.0f;
            float sum = e0 + e1;
#pragma unroll
            for (int o = 16; o; o >>= 1) sum += __shfl_xor_sync(~0u, sum, o);
            __syncthreads();
            if (lane == 0) pr[warp] = sum;
            __syncthreads();
            if (tid < 32) {
                float v = (tid < 8) ? pr[tid] : 0.0f;
#pragma unroll
                for (int o = 4; o; o >>= 1) v += __shfl_xor_sync(~0u, v, o);
                if (tid == 0) sh_sum = v;
            }
            __syncthreads();
            float inv = __fdividef(1.0f, sh_sum);
            float w0 = e0 * inv, w1 = e1 * inv;
            float c0 = 0.0f, c1 = 0.0f;
            if (tid < T_) {
                A_sm[b * T_ + tid] = w0;
                float2 cv = *(const float2*)(g_C + (b * T_ + tid) * 2);
                c0 = fmaf(w0, cv.x, c0); c1 = fmaf(w0, cv.y, c1);
            }
            if (tid + 256 < T_) {
                A_sm[b * T_ + tid + 256] = w1;
                float2 cv = *(const float2*)(g_C + (b * T_ + tid + 256) * 2);
                c0 = fmaf(w1, cv.x, c0); c1 = fmaf(w1, cv.y, c1);
            }
#pragma unroll
            for (int o = 16; o; o >>= 1) {
                c0 += __shfl_xor_sync(~0u, c0, o);
                c1 += __shfl_xor_sync(~0u, c1, o);
            }
            __syncthreads();
            if (lane == 0) { pr[warp] = c0; prB[warp] = c1; }
            __syncthreads();
            if (tid == 0) {
                float r0 = 0.0f, r1 = 0.0f;
#pragma unroll
                for (int i = 0; i < 8; i++) { r0 += pr[i]; r1 += prB[i]; }
                out[b * 2 + 0] = r0 + bc[0];
                out[b * 2 + 1] = r1 + bc[1];
            }
            __syncthreads();
        }
    }
}

// ============================================================================
// Launch. Output layout: [out (B*2) | A_sm (B*T) | A_t raw logits (B*T)]
// ============================================================================
extern "C" void kernel_launch(void* const* d_in, const int* in_sizes, int n_in,
                              void* d_out, int out_size)
{
    const float* H  = (const float*)d_in[0];
    const float* Wv = (const float*)d_in[1];
    const float* bv = (const float*)d_in[2];
    const float* Wu = (const float*)d_in[3];
    const float* bu = (const float*)d_in[4];
    const float* Wa = (const float*)d_in[5];
    const float* ba = (const float*)d_in[6];
    const float* Wc = (const float*)d_in[7];
    const float* bc = (const float*)d_in[8];

    float* out   = (float*)d_out;
    float* A_sm  = out + B_ * 2;
    float* A_raw = A_sm + B_ * T_;

    cudaFuncSetAttribute(gemm_attn_kernel,
                         cudaFuncAttributeMaxDynamicSharedMemorySize, DYN);

    prep_kernel<<<64, 256>>>(Wv, Wu);
    gemm_attn_kernel<<<GRID, 256, DYN>>>(H, bv, bu, Wa, ba, Wc, bc,
                                         A_raw, A_sm, out);
}